// round 13
// baseline (speedup 1.0000x reference)
#include <cuda_runtime.h>
#include <cuda_fp16.h>
#include <cstdint>

// ---------------- problem constants ----------------
constexpr int SEQ  = 2048;
constexpr int HID  = 2048;
constexpr int NHEAD = 32;
constexpr int NKVH  = 8;
constexpr int HDIM  = 64;
constexpr int RLEN  = 1024;
constexpr int KVTOT = RLEN + SEQ;   // 3072
constexpr int NQKV  = NHEAD * HDIM + 2 * NKVH * HDIM;  // 3072
constexpr float SCALE = 0.125f;
constexpr float LOG2E = 1.44269504088896340736f;

// ---------------- scratch (device globals; no allocs) ----------------
__device__ __half g_hth [SEQ * HID];            // hidden fp16
__device__ __half g_wqkv[HID * NQKV];           // Wq|Wk|Wv fp16 [k][n]
__device__ __half g_woh [HID * HID];            // Wo fp16 [k][n]
__device__ __half g_qh  [SEQ * NHEAD * HDIM];   // roped Q fp16, pre-scaled by SCALE*log2(e)
__device__ __half g_kc  [NKVH * KVTOT * HDIM];  // unified K [hk][tok][d] fp16
__device__ __half g_vc  [NKVH * KVTOT * HDIM];  // unified V [hk][tok][d] fp16
__device__ __half g_ao  [SEQ * NHEAD * HDIM];   // attention out fp16

// ---------------- helpers ----------------
__device__ __forceinline__ unsigned packh2(float x, float y) {
    __half2 h = __floats2half2_rn(x, y);
    return *(unsigned*)&h;
}
__device__ __forceinline__ float ex2(float x) {
    float r;
    asm("ex2.approx.f32 %0, %1;" : "=f"(r) : "f"(x));
    return r;
}
__device__ __forceinline__ unsigned h2ex2(unsigned x) {
    unsigned r;
    asm("ex2.approx.f16x2 %0, %1;" : "=r"(r) : "r"(x));
    return r;
}
__device__ __forceinline__ void mma16(float* c, const unsigned* a, const unsigned* b) {
    asm volatile(
        "mma.sync.aligned.m16n8k16.row.col.f32.f16.f16.f32 "
        "{%0,%1,%2,%3},{%4,%5,%6,%7},{%8,%9},{%0,%1,%2,%3};"
        : "+f"(c[0]), "+f"(c[1]), "+f"(c[2]), "+f"(c[3])
        : "r"(a[0]), "r"(a[1]), "r"(a[2]), "r"(a[3]), "r"(b[0]), "r"(b[1]));
}
__device__ __forceinline__ void ldsm_x4(unsigned* r, unsigned addr) {
    asm volatile("ldmatrix.sync.aligned.m8n8.x4.shared.b16 {%0,%1,%2,%3}, [%4];"
        : "=r"(r[0]), "=r"(r[1]), "=r"(r[2]), "=r"(r[3]) : "r"(addr));
}
__device__ __forceinline__ void ldsm_x4_t(unsigned* r, unsigned addr) {
    asm volatile("ldmatrix.sync.aligned.m8n8.x4.trans.shared.b16 {%0,%1,%2,%3}, [%4];"
        : "=r"(r[0]), "=r"(r[1]), "=r"(r[2]), "=r"(r[3]) : "r"(addr));
}
#define CP16(dst, src) asm volatile("cp.async.cg.shared.global [%0], [%1], 16;" :: "r"(dst), "l"(src))
#define CP_COMMIT()    asm volatile("cp.async.commit_group;")
#define CP_WAIT0()     asm volatile("cp.async.wait_group 0;")
#define CP_WAIT1()     asm volatile("cp.async.wait_group 1;")

// ================= fused conversion kernel (one launch for all prep) =================
constexpr int CONV_BLOCKS = 10752;

__global__ __launch_bounds__(256)
void conv_all(const float* __restrict__ hidden, const float* __restrict__ Wq,
              const float* __restrict__ Wk, const float* __restrict__ Wv,
              const float* __restrict__ Wo, const float* __restrict__ rk,
              const float* __restrict__ rv,
              __half* __restrict__ hth, __half* __restrict__ wqkv,
              __half* __restrict__ woh, __half* __restrict__ kc, __half* __restrict__ vc)
{
    const int b = blockIdx.x, tid = threadIdx.x;
    if (b < 4096) {                        // hidden or Wo, linear
        const float* src = (b < 2048) ? hidden : Wo;
        __half* dst = (b < 2048) ? hth : woh;
        int i = (b & 2047) * 256 + tid;    // 8-elem unit
        float4 a = ((const float4*)src)[2 * i], c = ((const float4*)src)[2 * i + 1];
        ((uint4*)dst)[i] = make_uint4(packh2(a.x, a.y), packh2(a.z, a.w),
                                      packh2(c.x, c.y), packh2(c.z, c.w));
    } else if (b < 8192) {                 // Wq
        int id = (b - 4096) * 256 + tid;
        int k = id >> 9, n4 = (id & 511) * 4;
        float4 v = *(const float4*)&Wq[(size_t)k * 2048 + n4];
        *(uint2*)&wqkv[(size_t)k * NQKV + n4] = make_uint2(packh2(v.x, v.y), packh2(v.z, v.w));
    } else if (b < 10240) {                // Wk / Wv
        const float* src = (b < 9216) ? Wk : Wv;
        const int noff = (b < 9216) ? 2048 : 2560;
        int id = ((b - 8192) & 1023) * 256 + tid;
        int k = id >> 7, n4 = (id & 127) * 4;
        float4 v = *(const float4*)&src[(size_t)k * 512 + n4];
        *(uint2*)&wqkv[(size_t)k * NQKV + noff + n4] = make_uint2(packh2(v.x, v.y), packh2(v.z, v.w));
    } else {                               // rk / rv -> ret region of kc / vc
        const float* src = (b < 10496) ? rk : rv;
        __half* dst = (b < 10496) ? kc : vc;
        int i = ((b - 10240) & 255) * 256 + tid;   // 8-elem unit
        int e = i * 8;
        int hk = e >> 16, rem = e & 65535;
        float4 a = *(const float4*)&src[e];
        float4 c = *(const float4*)&src[e + 4];
        *(uint4*)&dst[(size_t)hk * KVTOT * HDIM + rem] =
            make_uint4(packh2(a.x, a.y), packh2(a.z, a.w),
                       packh2(c.x, c.y), packh2(c.z, c.w));
    }
}

// ================= fp16 GEMM: BM=128 BN=256 BK=32, 8 warps (2m x 4n), warp 64x64 =================
constexpr int GA_STR = 40;              // halfwords; rows differ by 80B=5x16B -> conflict-free
constexpr int GB_STR = 264;             // halfwords; rows differ by 528B=33x16B -> conflict-free
constexpr int GA_HW  = 128 * GA_STR;    // 5120 per stage
constexpr int GB_HW  = 32 * GB_STR;     // 8448 per stage
constexpr int SMEM_H = 3 * (GA_HW + GB_HW) * 2;   // 81408 B

__device__ __forceinline__ void hgemm_main(
    const __half* __restrict__ A, const __half* __restrict__ B,
    int K, int N, int bm, int bn, int tid,
    unsigned as_u, unsigned bs_u, float acc[4][8][4])
{
    const int warp = tid >> 5;
    const int lane = tid & 31;
    const int m_base = (warp >> 2) * 64;
    const int n_base = (warp & 3) * 64;

    const int aRow = tid >> 2, aC = (tid & 3) * 8;
    const int bK   = tid >> 3, bN = (tid & 7) * 8;

    const int a_r = lane & 15, a_c = (lane >> 4) << 3;
    const int b_k = ((lane >> 3) & 1) * 8 + (lane & 7), b_n = (lane >> 4) << 3;

    auto issue = [&](int it, int s) {
        const size_t k0 = (size_t)it * 32;
        unsigned ad = as_u + (s * GA_HW + aRow * GA_STR + aC) * 2;
        CP16(ad,                   &A[(size_t)(bm + aRow) * K + k0 + aC]);
        CP16(ad + 64 * GA_STR * 2, &A[(size_t)(bm + aRow + 64) * K + k0 + aC]);
        unsigned bd = bs_u + (s * GB_HW + bK * GB_STR + bN) * 2;
#pragma unroll
        for (int j = 0; j < 4; j++)
            CP16(bd + j * 64 * 2, &B[(k0 + bK) * N + bn + bN + j * 64]);
    };

#pragma unroll
    for (int mt = 0; mt < 4; mt++)
#pragma unroll
        for (int nt = 0; nt < 8; nt++)
#pragma unroll
            for (int j = 0; j < 4; j++) acc[mt][nt][j] = 0.f;

    const int niter = K >> 5;
    issue(0, 0); CP_COMMIT();
    issue(1, 1); CP_COMMIT();

    for (int it = 0; it < niter; it++) {
        const int s = it % 3;
        CP_WAIT1();
        __syncthreads();

#pragma unroll
        for (int ks = 0; ks < 2; ks++) {
            const int kb = ks * 16;
            unsigned a[4][4];
#pragma unroll
            for (int mt = 0; mt < 4; mt++)
                ldsm_x4(a[mt], as_u + (s * GA_HW + (m_base + mt * 16 + a_r) * GA_STR + kb + a_c) * 2);
#pragma unroll
            for (int ng = 0; ng < 4; ng++) {
                unsigned b4[4];
                ldsm_x4_t(b4, bs_u + (s * GB_HW + (kb + b_k) * GB_STR + n_base + ng * 16 + b_n) * 2);
#pragma unroll
                for (int mt = 0; mt < 4; mt++) {
                    mma16(acc[mt][ng * 2],     a[mt], b4);
                    mma16(acc[mt][ng * 2 + 1], a[mt], b4 + 2);
                }
            }
        }
        if (it + 2 < niter) issue(it + 2, (it + 2) % 3);
        CP_COMMIT();
    }
}

// ---- fused QKV GEMM: epilogue applies rope + fp16 pack, scatters to qh/kc/vc ----
__global__ __launch_bounds__(256)
void hgemm_qkv(const __half* __restrict__ A, const __half* __restrict__ B,
               const float* __restrict__ cosb, const float* __restrict__ sinb,
               __half* __restrict__ qh, __half* __restrict__ kc, __half* __restrict__ vc)
{
    extern __shared__ __half smh[];
    const unsigned as_u = (unsigned)__cvta_generic_to_shared(smh);
    const unsigned bs_u = as_u + 3 * GA_HW * 2;
    const int tid = threadIdx.x;
    const int bm = blockIdx.y * 128, bn = blockIdx.x * 256;

    float acc[4][8][4];
    hgemm_main(A, B, HID, NQKV, bm, bn, tid, as_u, bs_u, acc);

    const int warp = tid >> 5, lane = tid & 31;
    const int gid = lane >> 2, tig = lane & 3;
    const int m_base = (warp >> 2) * 64;
    const int n_warp0 = bn + (warp & 3) * 64;   // 64-aligned: one head, one region

    if (n_warp0 < 2560) {
        // q or k: rope pairs (i, i+32) are (nt, nt+4) in-thread
        // q additionally pre-scaled by SCALE*log2(e) for the exp2 softmax
        const float sc = (n_warp0 < 2048) ? SCALE * LOG2E : 1.f;
#pragma unroll
        for (int mt = 0; mt < 4; mt++) {
#pragma unroll
            for (int half = 0; half < 2; half++) {
                const int row = bm + m_base + mt * 16 + gid + half * 8;   // token
                const int jo = half * 2;
#pragma unroll
                for (int nt = 0; nt < 4; nt++) {
                    const int i = nt * 8 + 2 * tig;
                    float2 cc = *(const float2*)&cosb[(size_t)row * 64 + i];
                    float2 ss = *(const float2*)&sinb[(size_t)row * 64 + i];
                    float x00 = acc[mt][nt][jo],     x01 = acc[mt][nt][jo + 1];
                    float x10 = acc[mt][nt + 4][jo], x11 = acc[mt][nt + 4][jo + 1];
                    unsigned lo = packh2((x00 * cc.x - x10 * ss.x) * sc,
                                         (x01 * cc.y - x11 * ss.y) * sc);
                    unsigned hi = packh2((x10 * cc.x + x00 * ss.x) * sc,
                                         (x11 * cc.y + x01 * ss.y) * sc);
                    __half* d0;
                    if (n_warp0 < 2048) {
                        d0 = qh + (size_t)row * 2048 + n_warp0 + i;
                    } else {
                        const int rel = n_warp0 - 2048 + i;
                        d0 = kc + ((size_t)(rel >> 6) * KVTOT + RLEN + row) * HDIM + (rel & 63);
                    }
                    *(unsigned*)d0        = lo;
                    *(unsigned*)(d0 + 32) = hi;
                }
            }
        }
    } else {
        // v region: fp16 store straight into unified vc[hk][RLEN+tok][d]
#pragma unroll
        for (int mt = 0; mt < 4; mt++) {
#pragma unroll
            for (int half = 0; half < 2; half++) {
                const int row = bm + m_base + mt * 16 + gid + half * 8;
                const int jo = half * 2;
#pragma unroll
                for (int nt = 0; nt < 8; nt++) {
                    const int rel = n_warp0 + nt * 8 + 2 * tig - 2560;
                    __half* d0 = vc + ((size_t)(rel >> 6) * KVTOT + RLEN + row) * HDIM + (rel & 63);
                    *(unsigned*)d0 = packh2(acc[mt][nt][jo], acc[mt][nt][jo + 1]);
                }
            }
        }
    }
}

// ---- Wo GEMM: fp32 out ----
__global__ __launch_bounds__(256)
void hgemm_out(const __half* __restrict__ A, const __half* __restrict__ B,
               float* __restrict__ C)
{
    extern __shared__ __half smh[];
    const unsigned as_u = (unsigned)__cvta_generic_to_shared(smh);
    const unsigned bs_u = as_u + 3 * GA_HW * 2;
    const int tid = threadIdx.x;
    const int bm = blockIdx.y * 128, bn = blockIdx.x * 256;

    float acc[4][8][4];
    hgemm_main(A, B, HID, HID, bm, bn, tid, as_u, bs_u, acc);

    const int warp = tid >> 5, lane = tid & 31;
    const int gid = lane >> 2, tig = lane & 3;
    const int m_base = (warp >> 2) * 64;
    const int n_base = (warp & 3) * 64;
#pragma unroll
    for (int mt = 0; mt < 4; mt++)
#pragma unroll
        for (int nt = 0; nt < 8; nt++) {
            int row = bm + m_base + mt * 16 + gid;
            int col = bn + n_base + nt * 8 + 2 * tig;
            *(float2*)&C[(size_t)row * HID + col]       = make_float2(acc[mt][nt][0], acc[mt][nt][1]);
            *(float2*)&C[(size_t)(row + 8) * HID + col] = make_float2(acc[mt][nt][2], acc[mt][nt][3]);
        }
}

// ================= fp16 flash attention: balanced paired q-tiles (R12, known-good) =================
constexpr int AT_STR = 72;
constexpr int AT_HW  = 64 * AT_STR;
constexpr int ATT_SMEM_BYTES = (AT_HW * 5) * 2;  // 46080 B

__global__ __launch_bounds__(128, 4)
void attn_tc(const __half* __restrict__ qh, const __half* __restrict__ kc,
             const __half* __restrict__ vc, __half* __restrict__ out)
{
    extern __shared__ __half sm[];
    const unsigned sm_u = (unsigned)__cvta_generic_to_shared(sm);

    const int bx   = blockIdx.x;           // 0..15 pair index
    const int h    = blockIdx.y;
    const int hk   = h >> 2;
    const int tid  = threadIdx.x;
    const int warp = tid >> 5;
    const int lane = tid & 31;
    const int gid  = lane >> 2;
    const int tig  = lane & 3;
    const int q0   = warp * 16;

    const int a_r = lane & 15, a_c = (lane >> 4) << 3;
    const int b_r = ((lane >> 4) << 3) + (lane & 7), b_c = ((lane >> 3) & 1) * 8;
    const int v_k = ((lane >> 3) & 1) * 8 + (lane & 7), v_n = (lane >> 4) << 3;

    const __half* kbase = kc + (size_t)hk * KVTOT * HDIM;
    const __half* vbase = vc + (size_t)hk * KVTOT * HDIM;

    const unsigned ONE2 = 0x3C003C00u;
    const unsigned ones2[2] = {ONE2, ONE2};

    for (int phase = 0; phase < 2; phase++) {
        const int t = phase ? (15 - bx) : (16 + bx);

        const int hasret = (t >= 1) ? 1 : 0;
        const int ntiles = (t + 1) + hasret;
        const int rb = ((t < 16) ? t : 16) - 1;

        auto tokbase_of = [&](int it) {
            return (hasret && it == 0) ? rb * 64 : RLEN + (it - hasret) * 64;
        };
        auto issue_kv = [&](int it, int s) {
            const int tb2 = tokbase_of(it);
            const unsigned koff = sm_u + (1 + 2 * s) * AT_HW * 2;
            const unsigned voff = koff + AT_HW * 2;
#pragma unroll
            for (int j = 0; j < 4; j++) {
                int id = tid + j * 128;
                int r = id >> 3, c8 = (id & 7) * 8;
                CP16(koff + (r * AT_STR + c8) * 2, &kbase[(size_t)(tb2 + r) * HDIM + c8]);
                CP16(voff + (r * AT_STR + c8) * 2, &vbase[(size_t)(tb2 + r) * HDIM + c8]);
            }
        };

#pragma unroll
        for (int j = 0; j < 4; j++) {
            int id = tid + j * 128;
            int r = id >> 3, c8 = (id & 7) * 8;
            CP16(sm_u + (r * AT_STR + c8) * 2,
                 &qh[(size_t)(t * 64 + r) * (NHEAD * HDIM) + h * HDIM + c8]);
        }
        issue_kv(0, 0);
        CP_COMMIT();

        unsigned qa[4][4];
        float m_lo = -1e30f, m_hi = -1e30f, l_lo = 0.f, l_hi = 0.f;
        float O[8][4];
#pragma unroll
        for (int nt = 0; nt < 8; nt++)
#pragma unroll
            for (int j = 0; j < 4; j++) O[nt][j] = 0.f;

        for (int it = 0; it < ntiles; it++) {
            const int s = it & 1;
            const bool isret = hasret && (it == 0);
            const int jt = it - hasret;

            if (it + 1 < ntiles) { issue_kv(it + 1, s ^ 1); CP_COMMIT(); CP_WAIT1(); }
            else                 { CP_WAIT0(); }
            __syncthreads();

            if (it == 0) {
#pragma unroll
                for (int kt = 0; kt < 4; kt++)
                    ldsm_x4(qa[kt], sm_u + ((q0 + a_r) * AT_STR + kt * 16 + a_c) * 2);
            }

            const unsigned koff = sm_u + (1 + 2 * s) * AT_HW * 2;
            const unsigned voff = koff + AT_HW * 2;

            float sacc[8][4];
#pragma unroll
            for (int nt = 0; nt < 8; nt++)
#pragma unroll
                for (int j = 0; j < 4; j++) sacc[nt][j] = 0.f;

#pragma unroll
            for (int kt = 0; kt < 4; kt++) {
                const int kb = kt * 16;
#pragma unroll
                for (int ng = 0; ng < 4; ng++) {
                    unsigned b4[4];
                    ldsm_x4(b4, koff + ((ng * 16 + b_r) * AT_STR + kb + b_c) * 2);
                    mma16(sacc[ng * 2],     qa[kt], b4);
                    mma16(sacc[ng * 2 + 1], qa[kt], b4 + 2);
                }
            }

            if (!isret) {
                const int s_lo = t * 64 + q0 + gid;
                const int s_hi = s_lo + 8;
#pragma unroll
                for (int nt = 0; nt < 8; nt++) {
#pragma unroll
                    for (int j = 0; j < 2; j++) {
                        int n = jt * 64 + nt * 8 + 2 * tig + j;
                        bool inval = (n < 1);
                        if (inval || n > s_lo) sacc[nt][j]     = -1e30f;
                        if (inval || n > s_hi) sacc[nt][j + 2] = -1e30f;
                    }
                }
            }

            float lm_lo = -1e30f, lm_hi = -1e30f;
#pragma unroll
            for (int nt = 0; nt < 8; nt++) {
                lm_lo = fmaxf(lm_lo, fmaxf(sacc[nt][0], sacc[nt][1]));
                lm_hi = fmaxf(lm_hi, fmaxf(sacc[nt][2], sacc[nt][3]));
            }
            lm_lo = fmaxf(lm_lo, __shfl_xor_sync(0xffffffffu, lm_lo, 1));
            lm_lo = fmaxf(lm_lo, __shfl_xor_sync(0xffffffffu, lm_lo, 2));
            lm_hi = fmaxf(lm_hi, __shfl_xor_sync(0xffffffffu, lm_hi, 1));
            lm_hi = fmaxf(lm_hi, __shfl_xor_sync(0xffffffffu, lm_hi, 2));
            const float mn_lo = fmaxf(m_lo, lm_lo);
            const float mn_hi = fmaxf(m_hi, lm_hi);

            unsigned plo[8], phi[8];
#pragma unroll
            for (int nt = 0; nt < 8; nt++) {
                plo[nt] = h2ex2(packh2(sacc[nt][0] - mn_lo, sacc[nt][1] - mn_lo));
                phi[nt] = h2ex2(packh2(sacc[nt][2] - mn_hi, sacc[nt][3] - mn_hi));
            }

            const float f_lo = ex2(m_lo - mn_lo);
            const float f_hi = ex2(m_hi - mn_hi);
            m_lo = mn_lo; m_hi = mn_hi;
#pragma unroll
            for (int nt = 0; nt < 8; nt++) {
                O[nt][0] *= f_lo; O[nt][1] *= f_lo;
                O[nt][2] *= f_hi; O[nt][3] *= f_hi;
            }

            float lacc[4] = {0.f, 0.f, 0.f, 0.f};
#pragma unroll
            for (int kt = 0; kt < 4; kt++) {
                unsigned pa[4] = {plo[2 * kt], phi[2 * kt], plo[2 * kt + 1], phi[2 * kt + 1]};
                mma16(lacc, pa, ones2);
#pragma unroll
                for (int ng = 0; ng < 4; ng++) {
                    unsigned b4[4];
                    ldsm_x4_t(b4, voff + ((kt * 16 + v_k) * AT_STR + ng * 16 + v_n) * 2);
                    mma16(O[ng * 2],     pa, b4);
                    mma16(O[ng * 2 + 1], pa, b4 + 2);
                }
            }
            l_lo = l_lo * f_lo + lacc[0];
            l_hi = l_hi * f_hi + lacc[2];
            __syncthreads();
        }

        const float inv_lo = (m_lo > -1e29f) ? (1.f / l_lo) : 0.f;
        const float inv_hi = (m_hi > -1e29f) ? (1.f / l_hi) : 0.f;
#pragma unroll
        for (int nt = 0; nt < 8; nt++) {
            int col = nt * 8 + 2 * tig;
            size_t r_lo = (size_t)(t * 64 + q0 + gid)     * (NHEAD * HDIM) + h * HDIM + col;
            size_t r_hi = (size_t)(t * 64 + q0 + gid + 8) * (NHEAD * HDIM) + h * HDIM + col;
            *(unsigned*)&out[r_lo] = packh2(O[nt][0] * inv_lo, O[nt][1] * inv_lo);
            *(unsigned*)&out[r_hi] = packh2(O[nt][2] * inv_hi, O[nt][3] * inv_hi);
        }
    }
}

// ---------------- launch ----------------
extern "C" void kernel_launch(void* const* d_in, const int* in_sizes, int n_in,
                              void* d_out, int out_size)
{
    const float* hidden = (const float*)d_in[0];
    const float* cosb   = (const float*)d_in[1];
    const float* sinb   = (const float*)d_in[2];
    const float* rk     = (const float*)d_in[3];
    const float* rv     = (const float*)d_in[4];
    const float* Wq     = (const float*)d_in[5];
    const float* Wk     = (const float*)d_in[6];
    const float* Wv     = (const float*)d_in[7];
    const float* Wo     = (const float*)d_in[8];
    float* out = (float*)d_out;

    __half *hth, *wqkv, *woh, *qh, *kc, *vc, *ao;
    cudaGetSymbolAddress((void**)&hth,  g_hth);
    cudaGetSymbolAddress((void**)&wqkv, g_wqkv);
    cudaGetSymbolAddress((void**)&woh,  g_woh);
    cudaGetSymbolAddress((void**)&qh,   g_qh);
    cudaGetSymbolAddress((void**)&kc,   g_kc);
    cudaGetSymbolAddress((void**)&vc,   g_vc);
    cudaGetSymbolAddress((void**)&ao,   g_ao);

    // 1. all fp16 conversions in one launch
    conv_all<<<CONV_BLOCKS, 256>>>(hidden, Wq, Wk, Wv, Wo, rk, rv,
                                   hth, wqkv, woh, kc, vc);

    // 2. fused QKV projection + rope epilogue (BM=128, BN=256)
    cudaFuncSetAttribute(hgemm_qkv, cudaFuncAttributeMaxDynamicSharedMemorySize, SMEM_H);
    hgemm_qkv<<<dim3(NQKV / 256, SEQ / 128), 256, SMEM_H>>>(hth, wqkv, cosb, sinb, qh, kc, vc);

    // 3. attention: balanced paired q-tiles, 1 head per CTA, 4 CTAs/SM
    cudaFuncSetAttribute(attn_tc, cudaFuncAttributeMaxDynamicSharedMemorySize, ATT_SMEM_BYTES);
    attn_tc<<<dim3(16, NHEAD), 128, ATT_SMEM_BYTES>>>(qh, kc, vc, ao);

    // 4. output projection (BM=128, BN=256)
    cudaFuncSetAttribute(hgemm_out, cudaFuncAttributeMaxDynamicSharedMemorySize, SMEM_H);
    hgemm_out<<<dim3(HID / 256, SEQ / 128), 256, SMEM_H>>>(ao, woh, out);
}